// round 1
// baseline (speedup 1.0000x reference)
#include <cuda_runtime.h>

#define N_NODES 20000
#define BATCH   512
#define EMBED   32
#define NS      5001
#define INV_TD  (1.0f/5000.0f)
#define LN2_F   0.6931471805599453f

// ---- scratch (no allocation allowed; __device__ globals) ----
__device__ __align__(16) float g_Ev0[N_NODES];  // exp(node_v0[n] * invpsi0)  (lambda_src, et=0)
__device__ __align__(16) float g_Ev1[N_NODES];  // exp(node_v1[n] * invpsi1)  (lambda_src, et=1)
__device__ __align__(16) float g_Eu0[N_NODES];  // exp(node_u0[n] * invpsi0)  (lambda_dst, et=0)
__device__ __align__(16) float g_Eu1[N_NODES];  // exp(node_u1[n] * invpsi1)  (lambda_dst, et=1)

__device__ float g_esrc[BATCH];    // exp((src_proj + b + c_src) * invpsi)
__device__ float g_edst[BATCH];    // exp((dst_proj + b + c_dst) * invpsi)
__device__ float g_coef[BATCH];    // psi_t * ln2   (for lg2-based softplus)
__device__ int   g_t[BATCH];       // event type bit
__device__ float g_gb[BATCH];      // base g for return-time integral
__device__ float g_al[BATCH];
__device__ float g_wt[BATCH];
__device__ float g_invpsi[BATCH];

// ============================================================================
// Kernel 1: per-node projections (warp per node) + per-batch constants (warp per b)
// ============================================================================
__global__ void prep_kernel(const float* __restrict__ emb,
                            const int*   __restrict__ assoc,
                            const int*   __restrict__ src,
                            const int*   __restrict__ pdst,
                            const float* __restrict__ last_update,
                            const float* __restrict__ cur_time,
                            const int*   __restrict__ et,
                            const float* __restrict__ W0,
                            const float* __restrict__ b0,
                            const float* __restrict__ W1,
                            const float* __restrict__ b1,
                            const float* __restrict__ psi,
                            const float* __restrict__ alpha,
                            const float* __restrict__ w_t)
{
    int warp = (blockIdx.x * blockDim.x + threadIdx.x) >> 5;
    int lane = threadIdx.x & 31;

    float invpsi0 = 1.0f / (psi[0] + 1e-7f);
    float invpsi1 = 1.0f / (psi[1] + 1e-7f);

    if (warp < N_NODES) {
        int n = warp;
        float e = emb[n * EMBED + lane];
        float p0u = e * W0[lane];
        float p0v = e * W0[EMBED + lane];
        float p1u = e * W1[lane];
        float p1v = e * W1[EMBED + lane];
        #pragma unroll
        for (int off = 16; off; off >>= 1) {
            p0u += __shfl_xor_sync(0xffffffffu, p0u, off);
            p0v += __shfl_xor_sync(0xffffffffu, p0v, off);
            p1u += __shfl_xor_sync(0xffffffffu, p1u, off);
            p1v += __shfl_xor_sync(0xffffffffu, p1v, off);
        }
        if (lane == 0) {
            g_Ev0[n] = __expf(p0v * invpsi0);
            g_Ev1[n] = __expf(p1v * invpsi1);
            g_Eu0[n] = __expf(p0u * invpsi0);
            g_Eu1[n] = __expf(p1u * invpsi1);
        }
    } else {
        int b = warp - N_NODES;
        if (b < BATCH) {
            int s = assoc[src[b]];
            int d = assoc[pdst[b]];
            float zs = emb[s * EMBED + lane];
            float zd = emb[d * EMBED + lane];
            float du0 = zs * W0[lane];
            float du1 = zs * W1[lane];
            float dv0 = zd * W0[EMBED + lane];
            float dv1 = zd * W1[EMBED + lane];
            #pragma unroll
            for (int off = 16; off; off >>= 1) {
                du0 += __shfl_xor_sync(0xffffffffu, du0, off);
                du1 += __shfl_xor_sync(0xffffffffu, du1, off);
                dv0 += __shfl_xor_sync(0xffffffffu, dv0, off);
                dv1 += __shfl_xor_sync(0xffffffffu, dv1, off);
            }
            if (lane == 0) {
                int   t  = (et[b] > 0) ? 1 : 0;
                float ps = psi[t];
                float al = alpha[t];
                float wt = w_t[t];
                float invpsi = 1.0f / (ps + 1e-7f);
                float ct  = cur_time[b];
                float tds = (ct - last_update[s]) * INV_TD;
                float tdd = (ct - last_update[d]) * INV_TD;
                float cs  = al * __expf(-wt * tds);
                float cd  = al * __expf(-wt * tdd);
                float du  = t ? du1 : du0;
                float dv  = t ? dv1 : dv0;
                float bb  = t ? b1[0] : b0[0];
                g_esrc[b]   = __expf((du + bb + cs) * invpsi);
                g_edst[b]   = __expf((dv + bb + cd) * invpsi);
                g_coef[b]   = ps * LN2_F;
                g_t[b]      = t;
                g_gb[b]     = du + dv + bb;
                g_al[b]     = al;
                g_wt[b]     = wt;
                g_invpsi[b] = invpsi;
            }
        }
    }
}

// ============================================================================
// Kernel 2: lambda_src[b,n] and lambda_dst[b,n]
//   lambda = psi*ln2 * lg2(1 + E[n] * e[b])
// ============================================================================
__global__ void __launch_bounds__(256) lambda_kernel(float* __restrict__ out)
{
    int i4 = blockIdx.x * blockDim.x + threadIdx.x;   // float4 index over N
    if (i4 >= N_NODES / 4) return;
    int b = blockIdx.y;

    int   t  = g_t[b];
    float es = g_esrc[b];
    float ed = g_edst[b];
    float cf = g_coef[b];

    const float4* __restrict__ Ev = (const float4*)(t ? g_Ev1 : g_Ev0);
    const float4* __restrict__ Eu = (const float4*)(t ? g_Eu1 : g_Eu0);
    float4 v = Ev[i4];
    float4 u = Eu[i4];

    float4 os, od;
    os.x = cf * __log2f(1.0f + v.x * es);
    os.y = cf * __log2f(1.0f + v.y * es);
    os.z = cf * __log2f(1.0f + v.z * es);
    os.w = cf * __log2f(1.0f + v.w * es);
    od.x = cf * __log2f(1.0f + u.x * ed);
    od.y = cf * __log2f(1.0f + u.y * ed);
    od.z = cf * __log2f(1.0f + u.z * ed);
    od.w = cf * __log2f(1.0f + u.w * ed);

    ((float4*)(out + (size_t)b * N_NODES))[i4] = os;
    ((float4*)(out + (size_t)(BATCH + b) * N_NODES))[i4] = od;
}

// ============================================================================
// Kernel 3: return_time_pred[b] — trapezoid of t * intensity * exp(-cumsum)
// One block (128 threads) per batch element; chunked block scan for cumsum.
// ============================================================================
#define RTP_THREADS 128
#define SPT 40   // 128*40 = 5120 >= 5001

__global__ void __launch_bounds__(RTP_THREADS) rtp_kernel(float* __restrict__ out)
{
    int b   = blockIdx.x;
    int tid = threadIdx.x;

    float gb     = g_gb[b];
    float al     = g_al[b];
    float wt     = g_wt[b];
    float invpsi = g_invpsi[b];
    float cf     = g_coef[b];

    float inten[SPT];
    int   i0   = tid * SPT;
    float lsum = 0.0f;
    #pragma unroll
    for (int k = 0; k < SPT; k++) {
        int i = i0 + k;
        float v = 0.0f;
        if (i < NS) {
            float x = (gb + al * __expf(-wt * (float)i * INV_TD)) * invpsi;
            v = cf * __log2f(1.0f + __expf(x));
        }
        inten[k] = v;
        lsum += v;
    }

    __shared__ float sh[RTP_THREADS];
    sh[tid] = lsum;
    __syncthreads();
    // Hillis-Steele inclusive scan over per-thread sums
    #pragma unroll
    for (int off = 1; off < RTP_THREADS; off <<= 1) {
        float mine = sh[tid];
        float add  = (tid >= off) ? sh[tid - off] : 0.0f;
        __syncthreads();
        sh[tid] = mine + add;
        __syncthreads();
    }
    float excl = sh[tid] - lsum;

    float integral = excl;
    float acc = 0.0f;
    #pragma unroll
    for (int k = 0; k < SPT; k++) {
        int i = i0 + k;
        integral += inten[k];
        if (i < NS) {
            float dens = inten[k] * __expf(-integral);
            float ts   = (float)i * dens;
            float w    = (i == 0 || i == NS - 1) ? 0.5f : 1.0f;
            acc += w * ts;
        }
    }

    __syncthreads();
    sh[tid] = acc;
    __syncthreads();
    #pragma unroll
    for (int off = RTP_THREADS / 2; off; off >>= 1) {
        if (tid < off) sh[tid] += sh[tid + off];
        __syncthreads();
    }
    if (tid == 0)
        out[(size_t)2 * BATCH * N_NODES + b] = sh[0];
}

// ============================================================================
extern "C" void kernel_launch(void* const* d_in, const int* in_sizes, int n_in,
                              void* d_out, int out_size)
{
    const float* emb   = (const float*)d_in[0];   // all_embeddings [N,32]
    const int*   assoc = (const int*)  d_in[1];   // [N]
    const int*   src   = (const int*)  d_in[2];   // [B]
    const int*   pdst  = (const int*)  d_in[3];   // [B]
    // d_in[4] = neg_dst (unused by reference)
    const float* lupd  = (const float*)d_in[5];   // last_update [N]
    const float* ctim  = (const float*)d_in[6];   // cur_time [B]
    const int*   et    = (const int*)  d_in[7];   // [B]
    const float* W0    = (const float*)d_in[8];   // [1,64]
    const float* b0    = (const float*)d_in[9];   // [1]
    const float* W1    = (const float*)d_in[10];  // [1,64]
    const float* b1    = (const float*)d_in[11];  // [1]
    const float* psi   = (const float*)d_in[12];  // [2]
    const float* alpha = (const float*)d_in[13];  // [2]
    const float* w_t   = (const float*)d_in[14];  // [2]
    float* out = (float*)d_out;

    // warps needed: N_NODES (node projections) + BATCH (per-b constants)
    int warps  = N_NODES + BATCH;
    int blocks = (warps + 7) / 8;   // 8 warps (256 threads) per block
    prep_kernel<<<blocks, 256>>>(emb, assoc, src, pdst, lupd, ctim, et,
                                 W0, b0, W1, b1, psi, alpha, w_t);

    dim3 lgrid((N_NODES / 4 + 255) / 256, BATCH);
    lambda_kernel<<<lgrid, 256>>>(out);

    rtp_kernel<<<BATCH, RTP_THREADS>>>(out);
}

// round 4
// speedup vs baseline: 1.5487x; 1.5487x over previous
#include <cuda_runtime.h>

#define N_NODES 20000
#define BATCH   512
#define EMBED   32
#define NS      5001
#define INV_TD  (1.0f/5000.0f)
#define LN2_F   0.6931471805599453f

#define TB       8                       // batch rows per lambda block
#define NF4      (N_NODES/4)             // 5000 float4 groups
#define LCHUNKS  ((NF4 + 255)/256)       // 20 node-chunks per b-group
#define BGROUPS  (BATCH/TB)              // 64
#define RTPB     BATCH                   // rtp blocks come first

// ---- scratch (__device__ globals; no allocation allowed) ----
__device__ __align__(16) float g_Ev0[N_NODES];
__device__ __align__(16) float g_Ev1[N_NODES];
__device__ __align__(16) float g_Eu0[N_NODES];
__device__ __align__(16) float g_Eu1[N_NODES];
__device__ __align__(16) float4 g_bc[BATCH];   // {esrc, edst, cf=psi*ln2, tflag}
__device__ __align__(16) float4 g_rc[BATCH];   // {gb, alpha, w_t, invpsi}

__device__ __forceinline__ float dot4(float4 a, float4 b) {
    return a.x*b.x + a.y*b.y + a.z*b.z + a.w*b.w;
}

// streaming (cache-last) 16B global store
__device__ __forceinline__ void st_cs_v4(float* p, float4 v) {
    asm volatile("st.global.cs.v4.f32 [%0], {%1, %2, %3, %4};"
                 :: "l"(p), "f"(v.x), "f"(v.y), "f"(v.z), "f"(v.w) : "memory");
}

// ============================================================================
// Kernel 1: prep. 8 lanes per item, 4 items per warp.
//   warps [0, 5000): node projections -> E tables
//   warps [5000, 5128): per-batch constants
// ============================================================================
__global__ void __launch_bounds__(256) prep_kernel(
    const float* __restrict__ emb,
    const int*   __restrict__ assoc,
    const int*   __restrict__ src,
    const int*   __restrict__ pdst,
    const float* __restrict__ last_update,
    const float* __restrict__ cur_time,
    const int*   __restrict__ et,
    const float* __restrict__ W0,
    const float* __restrict__ b0,
    const float* __restrict__ W1,
    const float* __restrict__ b1,
    const float* __restrict__ psi,
    const float* __restrict__ alpha,
    const float* __restrict__ w_t)
{
    int warp = (blockIdx.x * blockDim.x + threadIdx.x) >> 5;
    int lane = threadIdx.x & 31;
    int g    = lane >> 3;      // sub-item 0..3
    int j    = lane & 7;       // 8 lanes per item, each covers 4 dims

    const float4* W0f = (const float4*)W0;     // [16] : u=0..7, v=8..15
    const float4* W1f = (const float4*)W1;
    float4 w0u = W0f[j],     w1u = W1f[j];
    float4 w0v = W0f[8 + j], w1v = W1f[8 + j];

    float invpsi0 = 1.0f / (psi[0] + 1e-7f);
    float invpsi1 = 1.0f / (psi[1] + 1e-7f);

    if (warp < N_NODES/4) {
        int n = warp * 4 + g;
        float4 e = ((const float4*)(emb + n * EMBED))[j];
        float pu0 = dot4(e, w0u);
        float pv0 = dot4(e, w0v);
        float pu1 = dot4(e, w1u);
        float pv1 = dot4(e, w1v);
        #pragma unroll
        for (int off = 4; off; off >>= 1) {
            pu0 += __shfl_xor_sync(0xffffffffu, pu0, off);
            pv0 += __shfl_xor_sync(0xffffffffu, pv0, off);
            pu1 += __shfl_xor_sync(0xffffffffu, pu1, off);
            pv1 += __shfl_xor_sync(0xffffffffu, pv1, off);
        }
        if (j == 0) {
            g_Ev0[n] = __expf(pv0 * invpsi0);
            g_Ev1[n] = __expf(pv1 * invpsi1);
            g_Eu0[n] = __expf(pu0 * invpsi0);
            g_Eu1[n] = __expf(pu1 * invpsi1);
        }
    } else if (warp < N_NODES/4 + BATCH/4) {
        int b = (warp - N_NODES/4) * 4 + g;
        int s = assoc[src[b]];
        int d = assoc[pdst[b]];
        float4 zs = ((const float4*)(emb + s * EMBED))[j];
        float4 zd = ((const float4*)(emb + d * EMBED))[j];
        float du0 = dot4(zs, w0u);
        float du1 = dot4(zs, w1u);
        float dv0 = dot4(zd, w0v);
        float dv1 = dot4(zd, w1v);
        #pragma unroll
        for (int off = 4; off; off >>= 1) {
            du0 += __shfl_xor_sync(0xffffffffu, du0, off);
            du1 += __shfl_xor_sync(0xffffffffu, du1, off);
            dv0 += __shfl_xor_sync(0xffffffffu, dv0, off);
            dv1 += __shfl_xor_sync(0xffffffffu, dv1, off);
        }
        if (j == 0) {
            int   t  = (et[b] > 0) ? 1 : 0;
            float ps = psi[t];
            float al = alpha[t];
            float wt = w_t[t];
            float invpsi = t ? invpsi1 : invpsi0;
            float ct  = cur_time[b];
            float tds = (ct - last_update[s]) * INV_TD;
            float tdd = (ct - last_update[d]) * INV_TD;
            float cs  = al * __expf(-wt * tds);
            float cd  = al * __expf(-wt * tdd);
            float du  = t ? du1 : du0;
            float dv  = t ? dv1 : dv0;
            float bb  = t ? b1[0] : b0[0];
            float4 bc;
            bc.x = __expf((du + bb + cs) * invpsi);
            bc.y = __expf((dv + bb + cd) * invpsi);
            bc.z = ps * LN2_F;
            bc.w = (float)t;
            g_bc[b] = bc;
            float4 rc;
            rc.x = du + dv + bb;
            rc.y = al;
            rc.z = wt;
            rc.w = invpsi;
            g_rc[b] = rc;
        }
    }
}

// ============================================================================
// Kernel 2 (fused): blocks [0,512) do return_time_pred; the rest do lambda.
// ============================================================================
#define RTP_THREADS 256
#define SPT 20   // 256*20 = 5120 >= 5001

__global__ void __launch_bounds__(256) main_kernel(float* __restrict__ out)
{
    __shared__ float sh[RTP_THREADS];

    if (blockIdx.x < RTPB) {
        // ---------------- return_time_pred ----------------
        int b   = blockIdx.x;
        int tid = threadIdx.x;

        float4 rc = g_rc[b];
        float gb = rc.x, al = rc.y, wt = rc.z, invpsi = rc.w;
        float cf = g_bc[b].z;

        int   i0 = tid * SPT;
        float r  = __expf(-wt * INV_TD);            // per-step decay
        float e  = __expf(-wt * (float)i0 * INV_TD);

        float inten[SPT];
        float lsum = 0.0f;
        #pragma unroll
        for (int k = 0; k < SPT; k++) {
            int i = i0 + k;
            float v = 0.0f;
            if (i < NS) {
                float x = (gb + al * e) * invpsi;
                v = cf * __log2f(1.0f + __expf(x));
            }
            e *= r;
            inten[k] = v;
            lsum += v;
        }

        sh[tid] = lsum;
        __syncthreads();
        #pragma unroll
        for (int off = 1; off < RTP_THREADS; off <<= 1) {
            float mine = sh[tid];
            float add  = (tid >= off) ? sh[tid - off] : 0.0f;
            __syncthreads();
            sh[tid] = mine + add;
            __syncthreads();
        }
        float integral = sh[tid] - lsum;   // exclusive prefix

        float acc = 0.0f;
        #pragma unroll
        for (int k = 0; k < SPT; k++) {
            int i = i0 + k;
            integral += inten[k];
            if (i < NS) {
                float dens = inten[k] * __expf(-integral);
                float ts   = (float)i * dens;
                float w    = (i == 0 || i == NS - 1) ? 0.5f : 1.0f;
                acc += w * ts;
            }
        }

        __syncthreads();
        sh[tid] = acc;
        __syncthreads();
        #pragma unroll
        for (int off = RTP_THREADS / 2; off; off >>= 1) {
            if (tid < off) sh[tid] += sh[tid + off];
            __syncthreads();
        }
        if (tid == 0)
            out[(size_t)2 * BATCH * N_NODES + b] = sh[0];
        return;
    }

    // ---------------- lambda_src / lambda_dst, TB batch rows per block ------
    int id    = blockIdx.x - RTPB;
    int chunk = id % LCHUNKS;
    int bg    = id / LCHUNKS;
    int i4    = chunk * 256 + threadIdx.x;
    if (i4 >= NF4) return;

    float4 v0 = ((const float4*)g_Ev0)[i4];
    float4 v1 = ((const float4*)g_Ev1)[i4];
    float4 u0 = ((const float4*)g_Eu0)[i4];
    float4 u1 = ((const float4*)g_Eu1)[i4];

    #pragma unroll
    for (int bi = 0; bi < TB; bi++) {
        int b = bg * TB + bi;
        float4 bc = g_bc[b];
        float es = bc.x, ed = bc.y, cf = bc.z;
        bool  t  = (bc.w != 0.0f);
        float4 v = t ? v1 : v0;
        float4 u = t ? u1 : u0;

        float4 os, od;
        os.x = cf * __log2f(1.0f + v.x * es);
        os.y = cf * __log2f(1.0f + v.y * es);
        os.z = cf * __log2f(1.0f + v.z * es);
        os.w = cf * __log2f(1.0f + v.w * es);
        od.x = cf * __log2f(1.0f + u.x * ed);
        od.y = cf * __log2f(1.0f + u.y * ed);
        od.z = cf * __log2f(1.0f + u.z * ed);
        od.w = cf * __log2f(1.0f + u.w * ed);

        st_cs_v4(out + (size_t)b * N_NODES + i4 * 4, os);
        st_cs_v4(out + (size_t)(BATCH + b) * N_NODES + i4 * 4, od);
    }
}

// ============================================================================
extern "C" void kernel_launch(void* const* d_in, const int* in_sizes, int n_in,
                              void* d_out, int out_size)
{
    const float* emb   = (const float*)d_in[0];
    const int*   assoc = (const int*)  d_in[1];
    const int*   src   = (const int*)  d_in[2];
    const int*   pdst  = (const int*)  d_in[3];
    // d_in[4] = neg_dst (unused)
    const float* lupd  = (const float*)d_in[5];
    const float* ctim  = (const float*)d_in[6];
    const int*   et    = (const int*)  d_in[7];
    const float* W0    = (const float*)d_in[8];
    const float* b0    = (const float*)d_in[9];
    const float* W1    = (const float*)d_in[10];
    const float* b1    = (const float*)d_in[11];
    const float* psi   = (const float*)d_in[12];
    const float* alpha = (const float*)d_in[13];
    const float* w_t   = (const float*)d_in[14];
    float* out = (float*)d_out;

    int warps  = N_NODES/4 + BATCH/4;          // 5128
    int blocks = (warps + 7) / 8;              // 641 blocks of 256 threads
    prep_kernel<<<blocks, 256>>>(emb, assoc, src, pdst, lupd, ctim, et,
                                 W0, b0, W1, b1, psi, alpha, w_t);

    int grid = RTPB + LCHUNKS * BGROUPS;       // 512 + 1280 = 1792
    main_kernel<<<grid, 256>>>(out);
}